// round 4
// baseline (speedup 1.0000x reference)
#include <cuda_runtime.h>
#include <cstdint>
#include <math.h>

// ---------------- problem constants ----------------
#define NN      8192
#define FDIM    256
#define DSUB    64
#define KHOP    3
#define ODIM    128
#define COEFF   0.03125f           // d/(n*eps^2) = 64/(8192*0.25)
#define ETA_C   0.5f
#define LAPSC   0.15f              // ETA*LAMBDA_LAP
#define LN_EPSF 1e-5f

// ---------------- device scratch (no allocs allowed) ----------------
__device__ float g_Z[KHOP][NN][DSUB];           // 6.3 MB
__device__ float g_Gpart[KHOP][32][DSUB*DSUB];  // 1.6 MB
__device__ float g_R[KHOP];
__device__ float g_s[KHOP];                     // ETA*coeff*w[k]
__device__ float g_A[KHOP][DSUB][FDIM];         // M^{-1} W[k]
__device__ float g_Bs[KHOP][DSUB][ODIM];        // s_k * A_k @ Wout^T
__device__ float g_HW[NN*ODIM];                 // H @ Wout^T   (4 MB)
__device__ float g_LHW[NN*ODIM];                // L @ HW       (4 MB)

// ============================================================
// 1) Z[k] = hop_feats[k] @ W[k]^T
// ============================================================
__global__ __launch_bounds__(256) void compute_Z(const float* __restrict__ hop,
                                                 const float* __restrict__ Wst) {
    extern __shared__ float sm[];
    float* sH = sm;               // [64][257]
    float* sW = sm + 64 * 257;    // [64][257]
    const int tid = threadIdx.x;
    const int k = blockIdx.y;
    const int r0 = blockIdx.x * 64;

    const float* hp = hop + ((size_t)k * NN + r0) * FDIM;
    const float* wp = Wst + (size_t)k * DSUB * FDIM;
    for (int idx = tid * 4; idx < 64 * FDIM; idx += 1024) {
        int r = idx >> 8, c = idx & 255;
        float4 v = *(const float4*)(hp + idx);
        sH[r * 257 + c + 0] = v.x; sH[r * 257 + c + 1] = v.y;
        sH[r * 257 + c + 2] = v.z; sH[r * 257 + c + 3] = v.w;
        float4 w = *(const float4*)(wp + idx);
        sW[r * 257 + c + 0] = w.x; sW[r * 257 + c + 1] = w.y;
        sW[r * 257 + c + 2] = w.z; sW[r * 257 + c + 3] = w.w;
    }
    __syncthreads();

    const int tx = tid & 15, ty = tid >> 4;
    float acc[4][4] = {};
    #pragma unroll 4
    for (int f = 0; f < FDIM; f++) {
        float a[4], b[4];
        #pragma unroll
        for (int i = 0; i < 4; i++) a[i] = sH[(ty * 4 + i) * 257 + f];
        #pragma unroll
        for (int j = 0; j < 4; j++) b[j] = sW[(tx * 4 + j) * 257 + f];
        #pragma unroll
        for (int i = 0; i < 4; i++)
            #pragma unroll
            for (int j = 0; j < 4; j++) acc[i][j] += a[i] * b[j];
    }
    #pragma unroll
    for (int i = 0; i < 4; i++) {
        float4 o = make_float4(acc[i][0], acc[i][1], acc[i][2], acc[i][3]);
        *(float4*)&g_Z[k][r0 + ty * 4 + i][tx * 4] = o;
    }
}

// ============================================================
// 2) partial Gram: each block (32 per k) does 256 rows of Z^T Z
// ============================================================
__global__ __launch_bounds__(256) void compute_G(void) {
    __shared__ float sZ[16 * DSUB];
    const int tid = threadIdx.x;
    const int k = blockIdx.y;
    const int r0 = blockIdx.x * 256;
    const int tx = tid & 15, ty = tid >> 4;
    float acc[4][4] = {};

    for (int chunk = 0; chunk < 256; chunk += 16) {
        int lr = tid >> 4, lc = (tid & 15) * 4;
        *(float4*)&sZ[lr * DSUB + lc] = *(const float4*)&g_Z[k][r0 + chunk + lr][lc];
        __syncthreads();
        #pragma unroll
        for (int rr = 0; rr < 16; rr++) {
            float4 a = *(const float4*)&sZ[rr * DSUB + ty * 4];
            float4 b = *(const float4*)&sZ[rr * DSUB + tx * 4];
            float av[4] = {a.x, a.y, a.z, a.w};
            float bv[4] = {b.x, b.y, b.z, b.w};
            #pragma unroll
            for (int i = 0; i < 4; i++)
                #pragma unroll
                for (int j = 0; j < 4; j++) acc[i][j] += av[i] * bv[j];
        }
        __syncthreads();
    }
    #pragma unroll
    for (int i = 0; i < 4; i++)
        #pragma unroll
        for (int j = 0; j < 4; j++)
            g_Gpart[k][blockIdx.x][(ty * 4 + i) * DSUB + tx * 4 + j] = acc[i][j];
}

// ============================================================
// 3) per-k: reduce G, M = I + coeff*G, Cholesky, logdet, A = M^{-1} W[k]
// ============================================================
__global__ __launch_bounds__(256) void chol_solve(const float* __restrict__ Wst) {
    extern __shared__ float sm[];
    float* sM  = sm;                    // [64][65]
    float* sD  = sm + 64 * 65;          // [64] sqrt of diag
    float* inv = sD + 64;               // [64]
    float* sY  = inv + 64;              // [64][256]
    const int k = blockIdx.x, tid = threadIdx.x;

    for (int idx = tid; idx < DSUB * DSUB; idx += 256) {
        float s = 0.f;
        #pragma unroll 8
        for (int b = 0; b < 32; b++) s += g_Gpart[k][b][idx];
        int i = idx >> 6, j = idx & 63;
        sM[i * 65 + j] = (i == j ? 1.f : 0.f) + COEFF * s;
    }
    __syncthreads();

    for (int j = 0; j < DSUB; j++) {
        float d2 = sM[j * 65 + j];
        float dsq = sqrtf(d2);
        float dinv = 1.f / dsq;
        if (tid > j && tid < DSUB) sM[tid * 65 + j] *= dinv;   // diag never overwritten
        if (tid == 0) sD[j] = dsq;
        __syncthreads();
        int rem = 63 - j;
        for (int t = tid; t < rem * rem; t += 256) {
            int i = j + 1 + t / rem, p = j + 1 + t % rem;
            if (p <= i) sM[i * 65 + p] -= sM[i * 65 + j] * sM[p * 65 + j];
        }
        __syncthreads();
    }
    if (tid < DSUB) inv[tid] = 1.f / sD[tid];
    if (tid == 0) {
        float r = 0.f;
        for (int j = 0; j < DSUB; j++) r += logf(sD[j]);
        g_R[k] = r;    // == 0.5 * logdet
    }
    __syncthreads();

    const int c = tid;   // 256 RHS columns
    for (int i = 0; i < DSUB; i++) {
        float s = Wst[((size_t)k * DSUB + i) * FDIM + c];
        float s0 = 0.f, s1 = 0.f, s2 = 0.f, s3 = 0.f;
        int j = 0;
        for (; j + 4 <= i; j += 4) {
            s0 += sM[i * 65 + j + 0] * sY[(j + 0) * FDIM + c];
            s1 += sM[i * 65 + j + 1] * sY[(j + 1) * FDIM + c];
            s2 += sM[i * 65 + j + 2] * sY[(j + 2) * FDIM + c];
            s3 += sM[i * 65 + j + 3] * sY[(j + 3) * FDIM + c];
        }
        for (; j < i; j++) s0 += sM[i * 65 + j] * sY[j * FDIM + c];
        sY[i * FDIM + c] = (s - ((s0 + s1) + (s2 + s3))) * inv[i];
    }
    for (int i = DSUB - 1; i >= 0; i--) {
        float s = sY[i * FDIM + c];
        float s0 = 0.f, s1 = 0.f, s2 = 0.f, s3 = 0.f;
        int j = i + 1;
        for (; j + 4 <= DSUB; j += 4) {
            s0 += sM[(j + 0) * 65 + i] * sY[(j + 0) * FDIM + c];
            s1 += sM[(j + 1) * 65 + i] * sY[(j + 1) * FDIM + c];
            s2 += sM[(j + 2) * 65 + i] * sY[(j + 2) * FDIM + c];
            s3 += sM[(j + 3) * 65 + i] * sY[(j + 3) * FDIM + c];
        }
        for (; j < DSUB; j++) s0 += sM[j * 65 + i] * sY[j * FDIM + c];
        float x = (s - ((s0 + s1) + (s2 + s3))) * inv[i];
        sY[i * FDIM + c] = x;
        g_A[k][i][c] = x;
    }
}

// ============================================================
// 4) delta_R / dR_norm / softmax weights + output tail
// ============================================================
__global__ void finalize_w(const float* __restrict__ taup, float* __restrict__ out_tail) {
    if (threadIdx.x != 0) return;
    float R0 = g_R[0], R1 = g_R[1], R2 = g_R[2];
    float d0 = R0, d1 = R1 - R0, d2 = R2 - R1;
    float mean = (d0 + d1 + d2) * (1.f / 3.f);
    float e0 = d0 - mean, e1 = d1 - mean, e2 = d2 - mean;
    float sd = sqrtf((e0 * e0 + e1 * e1 + e2 * e2) * 0.5f);   // ddof=1
    float s = 1.f / (sd + 1e-6f);
    float n0 = e0 * s, n1 = e1 * s, n2 = e2 * s;
    float tau = taup[0];
    float a0 = n0 / tau, a1 = n1 / tau, a2 = n2 / tau;
    float mx = fmaxf(a0, fmaxf(a1, a2));
    float x0 = expf(a0 - mx), x1 = expf(a1 - mx), x2 = expf(a2 - mx);
    float isum = 1.f / (x0 + x1 + x2);
    float w0 = x0 * isum, w1 = x1 * isum, w2 = x2 * isum;
    out_tail[0] = w0; out_tail[1] = w1; out_tail[2] = w2;
    out_tail[3] = n0; out_tail[4] = n1; out_tail[5] = n2;
    out_tail[6] = d0; out_tail[7] = d1; out_tail[8] = d2;
    g_s[0] = ETA_C * COEFF * w0;
    g_s[1] = ETA_C * COEFF * w1;
    g_s[2] = ETA_C * COEFF * w2;
}

// ============================================================
// 5) Bs[k] = s_k * A[k] @ Wout^T   [3 x 64 x 128, tiny]
// ============================================================
__global__ __launch_bounds__(256) void computeB(const float* __restrict__ Wout) {
    __shared__ float sAt[16][68];   // A chunk transposed [f][d]
    __shared__ float sB[16][132];   // Wout chunk [f][col]
    const int tid = threadIdx.x;
    const int tx = tid & 15, ty = tid >> 4;
    const int k = blockIdx.x;
    float acc[4][8] = {};

    for (int f0 = 0; f0 < FDIM; f0 += 16) {
        int ar = tid >> 2, ac = (tid & 3) * 4;       // ar = d (0..63)
        float4 a = *(const float4*)&g_A[k][ar][f0 + ac];
        sAt[ac + 0][ar] = a.x; sAt[ac + 1][ar] = a.y;
        sAt[ac + 2][ar] = a.z; sAt[ac + 3][ar] = a.w;
        int bo = tid >> 1, bf = (tid & 1) * 8;       // bo = out col (0..127)
        const float* wpp = Wout + (size_t)bo * FDIM + f0 + bf;
        float4 b1 = *(const float4*)wpp;
        float4 b2 = *(const float4*)(wpp + 4);
        sB[bf + 0][bo] = b1.x; sB[bf + 1][bo] = b1.y;
        sB[bf + 2][bo] = b1.z; sB[bf + 3][bo] = b1.w;
        sB[bf + 4][bo] = b2.x; sB[bf + 5][bo] = b2.y;
        sB[bf + 6][bo] = b2.z; sB[bf + 7][bo] = b2.w;
        __syncthreads();
        #pragma unroll
        for (int kk = 0; kk < 16; kk++) {
            float ra[4], rb[8];
            *(float4*)&ra[0] = *(const float4*)&sAt[kk][ty * 4];
            *(float4*)&rb[0] = *(const float4*)&sB[kk][tx * 8];
            *(float4*)&rb[4] = *(const float4*)&sB[kk][tx * 8 + 4];
            #pragma unroll
            for (int i = 0; i < 4; i++)
                #pragma unroll
                for (int j = 0; j < 8; j++) acc[i][j] += ra[i] * rb[j];
        }
        __syncthreads();
    }
    float sk = g_s[k];
    #pragma unroll
    for (int i = 0; i < 4; i++) {
        int d = ty * 4 + i;
        #pragma unroll
        for (int j = 0; j < 8; j += 4) {
            float4 v = make_float4(sk * acc[i][j], sk * acc[i][j + 1],
                                   sk * acc[i][j + 2], sk * acc[i][j + 3]);
            *(float4*)&g_Bs[k][d][tx * 8 + j] = v;
        }
    }
}

// ============================================================
// 6) HW = H @ Wout^T  [8192 x 128, K=256]
// ============================================================
__global__ __launch_bounds__(256) void computeHW(const float* __restrict__ H,
                                                 const float* __restrict__ Wout) {
    __shared__ float sAt[16][68];
    __shared__ float sB[16][132];
    const int tid = threadIdx.x;
    const int tx = tid & 15, ty = tid >> 4;
    const int r0 = blockIdx.x * 64;
    float acc[4][8] = {};

    for (int f0 = 0; f0 < FDIM; f0 += 16) {
        int ar = tid >> 2, ac = (tid & 3) * 4;
        float4 a = *(const float4*)&H[(size_t)(r0 + ar) * FDIM + f0 + ac];
        sAt[ac + 0][ar] = a.x; sAt[ac + 1][ar] = a.y;
        sAt[ac + 2][ar] = a.z; sAt[ac + 3][ar] = a.w;
        int bo = tid >> 1, bf = (tid & 1) * 8;
        const float* wpp = Wout + (size_t)bo * FDIM + f0 + bf;
        float4 b1 = *(const float4*)wpp;
        float4 b2 = *(const float4*)(wpp + 4);
        sB[bf + 0][bo] = b1.x; sB[bf + 1][bo] = b1.y;
        sB[bf + 2][bo] = b1.z; sB[bf + 3][bo] = b1.w;
        sB[bf + 4][bo] = b2.x; sB[bf + 5][bo] = b2.y;
        sB[bf + 6][bo] = b2.z; sB[bf + 7][bo] = b2.w;
        __syncthreads();
        #pragma unroll
        for (int kk = 0; kk < 16; kk++) {
            float ra[4], rb[8];
            *(float4*)&ra[0] = *(const float4*)&sAt[kk][ty * 4];
            *(float4*)&rb[0] = *(const float4*)&sB[kk][tx * 8];
            *(float4*)&rb[4] = *(const float4*)&sB[kk][tx * 8 + 4];
            #pragma unroll
            for (int i = 0; i < 4; i++)
                #pragma unroll
                for (int j = 0; j < 8; j++) acc[i][j] += ra[i] * rb[j];
        }
        __syncthreads();
    }
    #pragma unroll
    for (int i = 0; i < 4; i++) {
        size_t row = r0 + ty * 4 + i;
        *(float4*)&g_HW[row * ODIM + tx * 8]     = make_float4(acc[i][0], acc[i][1], acc[i][2], acc[i][3]);
        *(float4*)&g_HW[row * ODIM + tx * 8 + 4] = make_float4(acc[i][4], acc[i][5], acc[i][6], acc[i][7]);
    }
}

// ============================================================
// 7) LHW = L @ HW via mma.sync tf32 (m16n8k8)   [17.2 GF]
//    BM=64, BN=128, BK=32, grid 128 CTAs, 256 thr
//    warps 2x4 (m x n), warp tile 32x32
// ============================================================
#define GA_PAD 36
#define GB_PAD 136
#define SA2 (64 * GA_PAD)    // 2304 floats
#define SB2 (32 * GB_PAD)    // 4352 floats
#define G2_SMEM ((2 * (SA2 + SB2)) * 4)   // 53248 B

__device__ __forceinline__ uint32_t f2tf32(float x) {
    uint32_t r;
    asm("cvt.rna.tf32.f32 %0, %1;" : "=r"(r) : "f"(x));
    return r;
}
__device__ __forceinline__ void mma_tf32_16x8x8(float* c, const uint32_t* a,
                                                const uint32_t* b) {
    asm volatile(
        "mma.sync.aligned.m16n8k8.row.col.f32.tf32.tf32.f32 "
        "{%0,%1,%2,%3}, {%4,%5,%6,%7}, {%8,%9}, {%0,%1,%2,%3};"
        : "+f"(c[0]), "+f"(c[1]), "+f"(c[2]), "+f"(c[3])
        : "r"(a[0]), "r"(a[1]), "r"(a[2]), "r"(a[3]), "r"(b[0]), "r"(b[1]));
}

__global__ __launch_bounds__(256, 1) void gemmLHW(const float* __restrict__ L,
                                                  const float* __restrict__ HW,
                                                  float* __restrict__ LHWout) {
    extern __shared__ float smx[];
    float* sA = smx;                       // [2][64][36]
    float* sB = smx + 2 * SA2;             // [2][32][136]

    const int tid = threadIdx.x;
    const int lane = tid & 31;
    const int warp = tid >> 5;
    const int wm = (warp & 1) * 32;        // warp m-offset
    const int wn = (warp >> 1) * 32;       // warp n-offset
    const int m0 = blockIdx.x * 64;

    // A staging: 2 float4 per thread. row = (tid>>3)+q*32, col4 = tid&7
    const int a_r = tid >> 3, a_c = (tid & 7) * 4;
    const float* Ag = L + (size_t)(m0 + a_r) * NN + a_c;
    // B staging: 4 float4 per thread. krow = (tid>>5)+q*8, col4 = tid&31
    const int b_r = tid >> 5, b_c = (tid & 31) * 4;
    const float* Bg = HW + (size_t)b_r * ODIM + b_c;

    float acc[2][4][4] = {};   // [mt][nt][reg]

    float4 ra[2], rb[4];
    #pragma unroll
    for (int q = 0; q < 2; q++) ra[q] = *(const float4*)(Ag + (size_t)q * 32 * NN);
    #pragma unroll
    for (int q = 0; q < 4; q++) rb[q] = *(const float4*)(Bg + (size_t)q * 8 * ODIM);

    auto stage = [&](int buf) {
        float* pa = sA + buf * SA2;
        float* pb = sB + buf * SB2;
        #pragma unroll
        for (int q = 0; q < 2; q++) {
            uint32_t* da = (uint32_t*)&pa[(a_r + q * 32) * GA_PAD + a_c];
            da[0] = f2tf32(ra[q].x); da[1] = f2tf32(ra[q].y);
            da[2] = f2tf32(ra[q].z); da[3] = f2tf32(ra[q].w);
        }
        #pragma unroll
        for (int q = 0; q < 4; q++) {
            uint32_t* db = (uint32_t*)&pb[(b_r + q * 8) * GB_PAD + b_c];
            db[0] = f2tf32(rb[q].x); db[1] = f2tf32(rb[q].y);
            db[2] = f2tf32(rb[q].z); db[3] = f2tf32(rb[q].w);
        }
    };

    stage(0);
    __syncthreads();

    const int NITER = NN / 32;   // 256
    for (int it = 0; it < NITER; it++) {
        if (it + 1 < NITER) {
            const float* Ag2 = Ag + (size_t)(it + 1) * 32;
            const float* Bg2 = Bg + (size_t)(it + 1) * 32 * ODIM;
            #pragma unroll
            for (int q = 0; q < 2; q++) ra[q] = *(const float4*)(Ag2 + (size_t)q * 32 * NN);
            #pragma unroll
            for (int q = 0; q < 4; q++) rb[q] = *(const float4*)(Bg2 + (size_t)q * 8 * ODIM);
        }
        const int buf = it & 1;
        const uint32_t* pa = (const uint32_t*)(sA + buf * SA2);
        const uint32_t* pb = (const uint32_t*)(sB + buf * SB2);
        #pragma unroll
        for (int ks = 0; ks < 4; ks++) {
            const int kk = ks * 8 + (lane & 3);
            uint32_t af[2][4], bf[4][2];
            #pragma unroll
            for (int mt = 0; mt < 2; mt++) {
                const int r = wm + mt * 16 + (lane >> 2);
                af[mt][0] = pa[r * GA_PAD + kk];
                af[mt][1] = pa[(r + 8) * GA_PAD + kk];
                af[mt][2] = pa[r * GA_PAD + kk + 4];
                af[mt][3] = pa[(r + 8) * GA_PAD + kk + 4];
            }
            #pragma unroll
            for (int nt = 0; nt < 4; nt++) {
                const int n = wn + nt * 8 + (lane >> 2);
                bf[nt][0] = pb[kk * GB_PAD + n];
                bf[nt][1] = pb[(kk + 4) * GB_PAD + n];
            }
            #pragma unroll
            for (int mt = 0; mt < 2; mt++)
                #pragma unroll
                for (int nt = 0; nt < 4; nt++)
                    mma_tf32_16x8x8(acc[mt][nt], af[mt], bf[nt]);
        }
        if (it + 1 < NITER) stage((it + 1) & 1);
        __syncthreads();
    }

    const int er = lane >> 2, ec = (lane & 3) * 2;
    #pragma unroll
    for (int mt = 0; mt < 2; mt++) {
        #pragma unroll
        for (int nt = 0; nt < 4; nt++) {
            const int row = m0 + wm + mt * 16 + er;
            const int col = wn + nt * 8 + ec;
            *(float2*)&LHWout[(size_t)row * ODIM + col] =
                make_float2(acc[mt][nt][0], acc[mt][nt][1]);
            *(float2*)&LHWout[(size_t)(row + 8) * ODIM + col] =
                make_float2(acc[mt][nt][2], acc[mt][nt][3]);
        }
    }
}

// ============================================================
// 8) H_pre = HW + sum_k Z_k @ Bs_k - 0.15*LHW ; soft-thr ; LayerNorm
// ============================================================
__global__ __launch_bounds__(256) void fuse_out(const float* __restrict__ thrP,
                                                const float* __restrict__ gamP,
                                                const float* __restrict__ betP,
                                                float* __restrict__ out) {
    __shared__ float sAt[16][68];   // Z chunk transposed [d][row]
    __shared__ float sB[16][132];   // Bs chunk [d][col]
    const int tid = threadIdx.x;
    const int tx = tid & 15, ty = tid >> 4;
    const int r0 = blockIdx.x * 64;
    float acc[4][8] = {};

    for (int k = 0; k < KHOP; k++) {
        for (int d0 = 0; d0 < DSUB; d0 += 16) {
            int ar = tid >> 2, ac = (tid & 3) * 4;      // ar = local row (0..63)
            float4 a = *(const float4*)&g_Z[k][r0 + ar][d0 + ac];
            sAt[ac + 0][ar] = a.x; sAt[ac + 1][ar] = a.y;
            sAt[ac + 2][ar] = a.z; sAt[ac + 3][ar] = a.w;
            int dl = tid >> 4, c8 = (tid & 15) * 8;     // dl = local d (0..15)
            float4 b1 = *(const float4*)&g_Bs[k][d0 + dl][c8];
            float4 b2 = *(const float4*)&g_Bs[k][d0 + dl][c8 + 4];
            *(float4*)&sB[dl][c8]     = b1;
            *(float4*)&sB[dl][c8 + 4] = b2;
            __syncthreads();
            #pragma unroll
            for (int kk = 0; kk < 16; kk++) {
                float ra[4], rb[8];
                *(float4*)&ra[0] = *(const float4*)&sAt[kk][ty * 4];
                *(float4*)&rb[0] = *(const float4*)&sB[kk][tx * 8];
                *(float4*)&rb[4] = *(const float4*)&sB[kk][tx * 8 + 4];
                #pragma unroll
                for (int i = 0; i < 4; i++)
                    #pragma unroll
                    for (int j = 0; j < 8; j++) acc[i][j] += ra[i] * rb[j];
            }
            __syncthreads();
        }
    }

    float thr_[8], gam_[8], bet_[8];
    #pragma unroll
    for (int j = 0; j < 8; j++) {
        int c = tx * 8 + j;
        thr_[j] = fabsf(__ldg(&thrP[c]));
        gam_[j] = __ldg(&gamP[c]);
        bet_[j] = __ldg(&betP[c]);
    }
    #pragma unroll
    for (int i = 0; i < 4; i++) {
        size_t row = r0 + ty * 4 + i;
        float4 hw1 = *(const float4*)&g_HW[row * ODIM + tx * 8];
        float4 hw2 = *(const float4*)&g_HW[row * ODIM + tx * 8 + 4];
        float4 lw1 = *(const float4*)&g_LHW[row * ODIM + tx * 8];
        float4 lw2 = *(const float4*)&g_LHW[row * ODIM + tx * 8 + 4];
        float bias[8] = {hw1.x - LAPSC * lw1.x, hw1.y - LAPSC * lw1.y,
                         hw1.z - LAPSC * lw1.z, hw1.w - LAPSC * lw1.w,
                         hw2.x - LAPSC * lw2.x, hw2.y - LAPSC * lw2.y,
                         hw2.z - LAPSC * lw2.z, hw2.w - LAPSC * lw2.w};
        float v[8], s = 0.f, q = 0.f;
        #pragma unroll
        for (int j = 0; j < 8; j++) {
            float p = acc[i][j] + bias[j];
            float ap = fabsf(p) - thr_[j];
            float val = ap > 0.f ? copysignf(ap, p) : 0.f;
            v[j] = val; s += val; q += val * val;
        }
        #pragma unroll
        for (int o = 8; o >= 1; o >>= 1) {
            s += __shfl_xor_sync(0xffffffffu, s, o);
            q += __shfl_xor_sync(0xffffffffu, q, o);
        }
        float mu = s * (1.f / 128.f);
        float var = q * (1.f / 128.f) - mu * mu;
        float rs = rsqrtf(var + LN_EPSF);
        float o_[8];
        #pragma unroll
        for (int j = 0; j < 8; j++) o_[j] = (v[j] - mu) * rs * gam_[j] + bet_[j];
        *(float4*)&out[row * ODIM + tx * 8]     = make_float4(o_[0], o_[1], o_[2], o_[3]);
        *(float4*)&out[row * ODIM + tx * 8 + 4] = make_float4(o_[4], o_[5], o_[6], o_[7]);
    }
}

// ============================================================
extern "C" void kernel_launch(void* const* d_in, const int* in_sizes, int n_in,
                              void* d_out, int out_size) {
    const float* H    = (const float*)d_in[0];
    const float* hop  = (const float*)d_in[1];
    const float* L    = (const float*)d_in[2];
    const float* Wst  = (const float*)d_in[3];
    const float* Wout = (const float*)d_in[4];
    const float* thr  = (const float*)d_in[5];
    const float* gam  = (const float*)d_in[6];
    const float* bet  = (const float*)d_in[7];
    const float* tau  = (const float*)d_in[8];
    float* out = (float*)d_out;
    float* out_tail = out + (size_t)NN * ODIM;

    float* d_HW;
    cudaGetSymbolAddress((void**)&d_HW, g_HW);
    float* d_LHW;
    cudaGetSymbolAddress((void**)&d_LHW, g_LHW);

    const int zsmem = 2 * 64 * 257 * 4;                           // 131584
    const int csmem = (64 * 65 + 64 + 64 + 64 * 256) * 4;         // 82688
    cudaFuncSetAttribute(compute_Z,  cudaFuncAttributeMaxDynamicSharedMemorySize, zsmem);
    cudaFuncSetAttribute(chol_solve, cudaFuncAttributeMaxDynamicSharedMemorySize, csmem);
    cudaFuncSetAttribute(gemmLHW,    cudaFuncAttributeMaxDynamicSharedMemorySize, G2_SMEM);

    compute_Z<<<dim3(128, KHOP), 256, zsmem>>>(hop, Wst);    // 1
    computeHW<<<128, 256>>>(H, Wout);                        // 2
    compute_G<<<dim3(32, KHOP), 256>>>();                    // 3
    chol_solve<<<KHOP, 256, csmem>>>(Wst);                   // 4
    finalize_w<<<1, 32>>>(tau, out_tail);                    // 5
    computeB<<<KHOP, 256>>>(Wout);                           // 6
    gemmLHW<<<128, 256, G2_SMEM>>>(L, d_HW, d_LHW);          // 7
    fuse_out<<<128, 256>>>(thr, gam, bet, out);              // 8
}

// round 5
// speedup vs baseline: 1.5463x; 1.5463x over previous
#include <cuda_runtime.h>
#include <cstdint>
#include <math.h>

// ---------------- problem constants ----------------
#define NN      8192
#define FDIM    256
#define DSUB    64
#define KHOP    3
#define ODIM    128
#define COEFF   0.03125f           // d/(n*eps^2) = 64/(8192*0.25)
#define ETA_C   0.5f
#define LAPSC   0.15f              // ETA*LAMBDA_LAP
#define LN_EPSF 1e-5f

// ---------------- device scratch (no allocs allowed) ----------------
__device__ float g_Z[KHOP][NN][DSUB];           // 6.3 MB
__device__ float g_Gpart[KHOP][32][DSUB*DSUB];  // 1.6 MB
__device__ float g_R[KHOP];
__device__ float g_s[KHOP];                     // ETA*coeff*w[k]
__device__ float g_Lf[KHOP][DSUB*65];           // Chol factor, diag = 1/sqrt
__device__ float g_WWo[KHOP][DSUB][ODIM];       // W[k] @ Wout^T
__device__ float g_Bs[KHOP][DSUB][ODIM];        // s_k * M^{-1} WWo
__device__ float g_HW[NN*ODIM];                 // H @ Wout^T   (4 MB)
__device__ float g_LHW[NN*ODIM];                // L @ HW       (4 MB)

// ============================================================
// 1) Z[k] = hop_feats[k] @ W[k]^T
// ============================================================
__global__ __launch_bounds__(256) void compute_Z(const float* __restrict__ hop,
                                                 const float* __restrict__ Wst) {
    extern __shared__ float sm[];
    float* sH = sm;               // [64][257]
    float* sW = sm + 64 * 257;    // [64][257]
    const int tid = threadIdx.x;
    const int k = blockIdx.y;
    const int r0 = blockIdx.x * 64;

    const float* hp = hop + ((size_t)k * NN + r0) * FDIM;
    const float* wp = Wst + (size_t)k * DSUB * FDIM;
    for (int idx = tid * 4; idx < 64 * FDIM; idx += 1024) {
        int r = idx >> 8, c = idx & 255;
        float4 v = *(const float4*)(hp + idx);
        sH[r * 257 + c + 0] = v.x; sH[r * 257 + c + 1] = v.y;
        sH[r * 257 + c + 2] = v.z; sH[r * 257 + c + 3] = v.w;
        float4 w = *(const float4*)(wp + idx);
        sW[r * 257 + c + 0] = w.x; sW[r * 257 + c + 1] = w.y;
        sW[r * 257 + c + 2] = w.z; sW[r * 257 + c + 3] = w.w;
    }
    __syncthreads();

    const int tx = tid & 15, ty = tid >> 4;
    float acc[4][4] = {};
    #pragma unroll 4
    for (int f = 0; f < FDIM; f++) {
        float a[4], b[4];
        #pragma unroll
        for (int i = 0; i < 4; i++) a[i] = sH[(ty * 4 + i) * 257 + f];
        #pragma unroll
        for (int j = 0; j < 4; j++) b[j] = sW[(tx * 4 + j) * 257 + f];
        #pragma unroll
        for (int i = 0; i < 4; i++)
            #pragma unroll
            for (int j = 0; j < 4; j++) acc[i][j] += a[i] * b[j];
    }
    #pragma unroll
    for (int i = 0; i < 4; i++) {
        float4 o = make_float4(acc[i][0], acc[i][1], acc[i][2], acc[i][3]);
        *(float4*)&g_Z[k][r0 + ty * 4 + i][tx * 4] = o;
    }
}

// ============================================================
// 2) partial Gram: each block (32 per k) does 256 rows of Z^T Z
// ============================================================
__global__ __launch_bounds__(256) void compute_G(void) {
    __shared__ float sZ[16 * DSUB];
    const int tid = threadIdx.x;
    const int k = blockIdx.y;
    const int r0 = blockIdx.x * 256;
    const int tx = tid & 15, ty = tid >> 4;
    float acc[4][4] = {};

    for (int chunk = 0; chunk < 256; chunk += 16) {
        int lr = tid >> 4, lc = (tid & 15) * 4;
        *(float4*)&sZ[lr * DSUB + lc] = *(const float4*)&g_Z[k][r0 + chunk + lr][lc];
        __syncthreads();
        #pragma unroll
        for (int rr = 0; rr < 16; rr++) {
            float4 a = *(const float4*)&sZ[rr * DSUB + ty * 4];
            float4 b = *(const float4*)&sZ[rr * DSUB + tx * 4];
            float av[4] = {a.x, a.y, a.z, a.w};
            float bv[4] = {b.x, b.y, b.z, b.w};
            #pragma unroll
            for (int i = 0; i < 4; i++)
                #pragma unroll
                for (int j = 0; j < 4; j++) acc[i][j] += av[i] * bv[j];
        }
        __syncthreads();
    }
    #pragma unroll
    for (int i = 0; i < 4; i++)
        #pragma unroll
        for (int j = 0; j < 4; j++)
            g_Gpart[k][blockIdx.x][(ty * 4 + i) * DSUB + tx * 4 + j] = acc[i][j];
}

// ============================================================
// 3) WWo[k] = Wst[k] @ Wout^T  [64 x 128, K=256] -- tiny fp32
// ============================================================
__global__ __launch_bounds__(256) void computeWWo(const float* __restrict__ Wst,
                                                  const float* __restrict__ Wout) {
    __shared__ float sAt[16][68];   // W chunk transposed [f][d]
    __shared__ float sB[16][132];   // Wout chunk [f][col]
    const int tid = threadIdx.x;
    const int tx = tid & 15, ty = tid >> 4;
    const int k = blockIdx.x;
    float acc[4][8] = {};

    for (int f0 = 0; f0 < FDIM; f0 += 16) {
        int ar = tid >> 2, ac = (tid & 3) * 4;       // ar = d (0..63)
        float4 a = *(const float4*)&Wst[((size_t)k * DSUB + ar) * FDIM + f0 + ac];
        sAt[ac + 0][ar] = a.x; sAt[ac + 1][ar] = a.y;
        sAt[ac + 2][ar] = a.z; sAt[ac + 3][ar] = a.w;
        int bo = tid >> 1, bf = (tid & 1) * 8;       // bo = out col (0..127)
        const float* wpp = Wout + (size_t)bo * FDIM + f0 + bf;
        float4 b1 = *(const float4*)wpp;
        float4 b2 = *(const float4*)(wpp + 4);
        sB[bf + 0][bo] = b1.x; sB[bf + 1][bo] = b1.y;
        sB[bf + 2][bo] = b1.z; sB[bf + 3][bo] = b1.w;
        sB[bf + 4][bo] = b2.x; sB[bf + 5][bo] = b2.y;
        sB[bf + 6][bo] = b2.z; sB[bf + 7][bo] = b2.w;
        __syncthreads();
        #pragma unroll
        for (int kk = 0; kk < 16; kk++) {
            float ra[4], rb[8];
            *(float4*)&ra[0] = *(const float4*)&sAt[kk][ty * 4];
            *(float4*)&rb[0] = *(const float4*)&sB[kk][tx * 8];
            *(float4*)&rb[4] = *(const float4*)&sB[kk][tx * 8 + 4];
            #pragma unroll
            for (int i = 0; i < 4; i++)
                #pragma unroll
                for (int j = 0; j < 8; j++) acc[i][j] += ra[i] * rb[j];
        }
        __syncthreads();
    }
    #pragma unroll
    for (int i = 0; i < 4; i++) {
        int d = ty * 4 + i;
        *(float4*)&g_WWo[k][d][tx * 8]     = make_float4(acc[i][0], acc[i][1], acc[i][2], acc[i][3]);
        *(float4*)&g_WWo[k][d][tx * 8 + 4] = make_float4(acc[i][4], acc[i][5], acc[i][6], acc[i][7]);
    }
}

// ============================================================
// 4) chol_factor: reduce Gpart, M = I + coeff*G, Cholesky (no div/mod),
//    logdet -> g_R, export L (diag stores 1/sqrt) -> g_Lf
// ============================================================
__global__ __launch_bounds__(256) void chol_factor(void) {
    __shared__ float sM[DSUB * 65];
    __shared__ float sD[DSUB];
    const int k = blockIdx.x, tid = threadIdx.x;

    for (int idx = tid; idx < DSUB * DSUB; idx += 256) {
        float s = 0.f;
        #pragma unroll 8
        for (int b = 0; b < 32; b++) s += g_Gpart[k][b][idx];
        int i = idx >> 6, j = idx & 63;
        sM[i * 65 + j] = (i == j ? 1.f : 0.f) + COEFF * s;
    }
    __syncthreads();

    const int ui = tid >> 2;          // update row 0..63
    const int ub = tid & 3;           // update col base
    for (int j = 0; j < DSUB; j++) {
        // diag (j,j) is never overwritten -> race-free broadcast read
        float d2 = sM[j * 65 + j];
        float dinv = rsqrtf(d2);
        if (tid > j && tid < DSUB) sM[tid * 65 + j] *= dinv;
        if (tid == 0) sD[j] = d2;     // store d^2; log uses 0.5*log(d2)
        __syncthreads();
        if (ui > j) {
            float ci = sM[ui * 65 + j];
            #pragma unroll
            for (int qq = 0; qq < 16; qq++) {
                int p = ub + (qq << 2);
                if (p > j && p <= ui)
                    sM[ui * 65 + p] -= ci * sM[p * 65 + j];
            }
        }
        __syncthreads();
    }
    if (tid == 0) {
        float r = 0.f;
        #pragma unroll 4
        for (int j = 0; j < DSUB; j++) r += logf(sD[j]);
        g_R[k] = 0.5f * r;            // == 0.5 * logdet
    }
    // replace diag with 1/sqrt(d2) for the solver
    if (tid < DSUB) sM[tid * 65 + tid] = rsqrtf(sD[tid]);
    __syncthreads();
    for (int idx = tid; idx < DSUB * 65; idx += 256) g_Lf[k][idx] = sM[idx];
}

// ============================================================
// 5) delta_R / dR_norm / softmax weights + output tail
// ============================================================
__global__ void finalize_w(const float* __restrict__ taup, float* __restrict__ out_tail) {
    if (threadIdx.x != 0) return;
    float R0 = g_R[0], R1 = g_R[1], R2 = g_R[2];
    float d0 = R0, d1 = R1 - R0, d2 = R2 - R1;
    float mean = (d0 + d1 + d2) * (1.f / 3.f);
    float e0 = d0 - mean, e1 = d1 - mean, e2 = d2 - mean;
    float sd = sqrtf((e0 * e0 + e1 * e1 + e2 * e2) * 0.5f);   // ddof=1
    float s = 1.f / (sd + 1e-6f);
    float n0 = e0 * s, n1 = e1 * s, n2 = e2 * s;
    float tau = taup[0];
    float a0 = n0 / tau, a1 = n1 / tau, a2 = n2 / tau;
    float mx = fmaxf(a0, fmaxf(a1, a2));
    float x0 = expf(a0 - mx), x1 = expf(a1 - mx), x2 = expf(a2 - mx);
    float isum = 1.f / (x0 + x1 + x2);
    float w0 = x0 * isum, w1 = x1 * isum, w2 = x2 * isum;
    out_tail[0] = w0; out_tail[1] = w1; out_tail[2] = w2;
    out_tail[3] = n0; out_tail[4] = n1; out_tail[5] = n2;
    out_tail[6] = d0; out_tail[7] = d1; out_tail[8] = d2;
    g_s[0] = ETA_C * COEFF * w0;
    g_s[1] = ETA_C * COEFF * w1;
    g_s[2] = ETA_C * COEFF * w2;
}

// ============================================================
// 6) trisolve: Bs[k] = s_k * M^{-1} WWo[k]   (128 RHS)
//    dynamic smem: sL 64*65 + sY 64*132
// ============================================================
#define TRI_SMEM ((DSUB * 65 + DSUB * 132) * 4)
__global__ __launch_bounds__(128) void trisolve_B(void) {
    extern __shared__ float tsm[];
    float* sL = tsm;                  // [64][65], diag = 1/sqrt
    float* sY = tsm + DSUB * 65;      // [64][132]
    const int k = blockIdx.x, c = threadIdx.x;

    for (int idx = c; idx < DSUB * 65; idx += 128) sL[idx] = g_Lf[k][idx];
    __syncthreads();

    const float sk = g_s[k];
    for (int i = 0; i < DSUB; i++) {
        float s = g_WWo[k][i][c];
        float s0 = 0.f, s1 = 0.f, s2 = 0.f, s3 = 0.f;
        int j = 0;
        for (; j + 4 <= i; j += 4) {
            s0 += sL[i * 65 + j + 0] * sY[(j + 0) * 132 + c];
            s1 += sL[i * 65 + j + 1] * sY[(j + 1) * 132 + c];
            s2 += sL[i * 65 + j + 2] * sY[(j + 2) * 132 + c];
            s3 += sL[i * 65 + j + 3] * sY[(j + 3) * 132 + c];
        }
        for (; j < i; j++) s0 += sL[i * 65 + j] * sY[j * 132 + c];
        sY[i * 132 + c] = (s - ((s0 + s1) + (s2 + s3))) * sL[i * 65 + i];
    }
    for (int i = DSUB - 1; i >= 0; i--) {
        float s = sY[i * 132 + c];
        float s0 = 0.f, s1 = 0.f, s2 = 0.f, s3 = 0.f;
        int j = i + 1;
        for (; j + 4 <= DSUB; j += 4) {
            s0 += sL[(j + 0) * 65 + i] * sY[(j + 0) * 132 + c];
            s1 += sL[(j + 1) * 65 + i] * sY[(j + 1) * 132 + c];
            s2 += sL[(j + 2) * 65 + i] * sY[(j + 2) * 132 + c];
            s3 += sL[(j + 3) * 65 + i] * sY[(j + 3) * 132 + c];
        }
        for (; j < DSUB; j++) s0 += sL[j * 65 + i] * sY[j * 132 + c];
        float x = (s - ((s0 + s1) + (s2 + s3))) * sL[i * 65 + i];
        sY[i * 132 + c] = x;
        g_Bs[k][i][c] = sk * x;
    }
}

// ============================================================
// 7) HW = H @ Wout^T  [8192 x 128, K=256]
// ============================================================
__global__ __launch_bounds__(256) void computeHW(const float* __restrict__ H,
                                                 const float* __restrict__ Wout) {
    __shared__ float sAt[16][68];
    __shared__ float sB[16][132];
    const int tid = threadIdx.x;
    const int tx = tid & 15, ty = tid >> 4;
    const int r0 = blockIdx.x * 64;
    float acc[4][8] = {};

    for (int f0 = 0; f0 < FDIM; f0 += 16) {
        int ar = tid >> 2, ac = (tid & 3) * 4;
        float4 a = *(const float4*)&H[(size_t)(r0 + ar) * FDIM + f0 + ac];
        sAt[ac + 0][ar] = a.x; sAt[ac + 1][ar] = a.y;
        sAt[ac + 2][ar] = a.z; sAt[ac + 3][ar] = a.w;
        int bo = tid >> 1, bf = (tid & 1) * 8;
        const float* wpp = Wout + (size_t)bo * FDIM + f0 + bf;
        float4 b1 = *(const float4*)wpp;
        float4 b2 = *(const float4*)(wpp + 4);
        sB[bf + 0][bo] = b1.x; sB[bf + 1][bo] = b1.y;
        sB[bf + 2][bo] = b1.z; sB[bf + 3][bo] = b1.w;
        sB[bf + 4][bo] = b2.x; sB[bf + 5][bo] = b2.y;
        sB[bf + 6][bo] = b2.z; sB[bf + 7][bo] = b2.w;
        __syncthreads();
        #pragma unroll
        for (int kk = 0; kk < 16; kk++) {
            float ra[4], rb[8];
            *(float4*)&ra[0] = *(const float4*)&sAt[kk][ty * 4];
            *(float4*)&rb[0] = *(const float4*)&sB[kk][tx * 8];
            *(float4*)&rb[4] = *(const float4*)&sB[kk][tx * 8 + 4];
            #pragma unroll
            for (int i = 0; i < 4; i++)
                #pragma unroll
                for (int j = 0; j < 8; j++) acc[i][j] += ra[i] * rb[j];
        }
        __syncthreads();
    }
    #pragma unroll
    for (int i = 0; i < 4; i++) {
        size_t row = r0 + ty * 4 + i;
        *(float4*)&g_HW[row * ODIM + tx * 8]     = make_float4(acc[i][0], acc[i][1], acc[i][2], acc[i][3]);
        *(float4*)&g_HW[row * ODIM + tx * 8 + 4] = make_float4(acc[i][4], acc[i][5], acc[i][6], acc[i][7]);
    }
}

// ============================================================
// 8) LHW = L @ HW via mma.sync tf32 (m16n8k8)   [17.2 GF]
//    BM=64, BN=128(=ODIM), BK=64, grid 128 CTAs, 256 thr
//    warps 2x4 (m x n), warp tile 32x32, 64 MMAs/thread/stage
// ============================================================
#define GA_PAD 68
#define GB_PAD 136
#define SA2 (64 * GA_PAD)    // 4352 floats
#define SB2 (64 * GB_PAD)    // 8704 floats
#define G2_SMEM ((2 * (SA2 + SB2)) * 4)   // 104448 B

__device__ __forceinline__ uint32_t f2tf32(float x) {
    uint32_t r;
    asm("cvt.rna.tf32.f32 %0, %1;" : "=r"(r) : "f"(x));
    return r;
}
__device__ __forceinline__ void mma_tf32_16x8x8(float* c, const uint32_t* a,
                                                const uint32_t* b) {
    asm volatile(
        "mma.sync.aligned.m16n8k8.row.col.f32.tf32.tf32.f32 "
        "{%0,%1,%2,%3}, {%4,%5,%6,%7}, {%8,%9}, {%0,%1,%2,%3};"
        : "+f"(c[0]), "+f"(c[1]), "+f"(c[2]), "+f"(c[3])
        : "r"(a[0]), "r"(a[1]), "r"(a[2]), "r"(a[3]), "r"(b[0]), "r"(b[1]));
}

__global__ __launch_bounds__(256, 1) void gemmLHW(const float* __restrict__ L,
                                                  const float* __restrict__ HW,
                                                  float* __restrict__ LHWout) {
    extern __shared__ float smx[];
    float* sA = smx;                       // [2][64][68]  (m-major, k padded)
    float* sB = smx + 2 * SA2;             // [2][64][136] (k-major, n padded)

    const int tid = threadIdx.x;
    const int lane = tid & 31;
    const int warp = tid >> 5;
    const int wm = (warp & 1) * 32;        // warp m-offset
    const int wn = (warp >> 1) * 32;       // warp n-offset
    const int m0 = blockIdx.x * 64;

    // A: 64 rows x 64 k. thread: row = tid>>2, float col = (tid&3)*4 + 16q
    const int a_r = tid >> 2, a_c = (tid & 3) * 4;
    const float* Ag = L + (size_t)(m0 + a_r) * NN + a_c;
    // B: 64 k x 128 n. thread: k-row = (tid>>3) + 32h, float col = (tid&7)*4 + 32q
    const int b_r = tid >> 3, b_c = (tid & 7) * 4;
    const float* Bg = HW + (size_t)b_r * ODIM + b_c;

    float acc[2][4][4] = {};   // [mt][nt][reg]

    float4 ra[4], rb[8];
    #pragma unroll
    for (int q = 0; q < 4; q++) ra[q] = *(const float4*)(Ag + q * 16);
    #pragma unroll
    for (int h = 0; h < 2; h++)
        #pragma unroll
        for (int q = 0; q < 4; q++)
            rb[h * 4 + q] = *(const float4*)(Bg + (size_t)h * 32 * ODIM + q * 32);

    auto stage = [&](int buf) {
        float* pa = sA + buf * SA2;
        float* pb = sB + buf * SB2;
        #pragma unroll
        for (int q = 0; q < 4; q++) {
            uint32_t* da = (uint32_t*)&pa[a_r * GA_PAD + a_c + q * 16];
            da[0] = f2tf32(ra[q].x); da[1] = f2tf32(ra[q].y);
            da[2] = f2tf32(ra[q].z); da[3] = f2tf32(ra[q].w);
        }
        #pragma unroll
        for (int h = 0; h < 2; h++)
            #pragma unroll
            for (int q = 0; q < 4; q++) {
                uint32_t* db = (uint32_t*)&pb[(b_r + h * 32) * GB_PAD + b_c + q * 32];
                float4 v = rb[h * 4 + q];
                db[0] = f2tf32(v.x); db[1] = f2tf32(v.y);
                db[2] = f2tf32(v.z); db[3] = f2tf32(v.w);
            }
    };

    stage(0);
    __syncthreads();

    const int NITER = NN / 64;   // 128
    for (int it = 0; it < NITER; it++) {
        if (it + 1 < NITER) {
            const float* Ag2 = Ag + (size_t)(it + 1) * 64;
            const float* Bg2 = Bg + (size_t)(it + 1) * 64 * ODIM;
            #pragma unroll
            for (int q = 0; q < 4; q++) ra[q] = *(const float4*)(Ag2 + q * 16);
            #pragma unroll
            for (int h = 0; h < 2; h++)
                #pragma unroll
                for (int q = 0; q < 4; q++)
                    rb[h * 4 + q] = *(const float4*)(Bg2 + (size_t)h * 32 * ODIM + q * 32);
        }
        const int buf = it & 1;
        const uint32_t* pa = (const uint32_t*)(sA + buf * SA2);
        const uint32_t* pb = (const uint32_t*)(sB + buf * SB2);
        #pragma unroll
        for (int ks = 0; ks < 8; ks++) {
            const int kk = ks * 8 + (lane & 3);
            uint32_t af[2][4], bf[4][2];
            #pragma unroll
            for (int mt = 0; mt < 2; mt++) {
                const int r = wm + mt * 16 + (lane >> 2);
                af[mt][0] = pa[r * GA_PAD + kk];
                af[mt][1] = pa[(r + 8) * GA_PAD + kk];
                af[mt][2] = pa[r * GA_PAD + kk + 4];
                af[mt][3] = pa[(r + 8) * GA_PAD + kk + 4];
            }
            #pragma unroll
            for (int nt = 0; nt < 4; nt++) {
                const int n = wn + nt * 8 + (lane >> 2);
                bf[nt][0] = pb[kk * GB_PAD + n];
                bf[nt][1] = pb[(kk + 4) * GB_PAD + n];
            }
            #pragma unroll
            for (int mt = 0; mt < 2; mt++)
                #pragma unroll
                for (int nt = 0; nt < 4; nt++)
                    mma_tf32_16x8x8(acc[mt][nt], af[mt], bf[nt]);
        }
        if (it + 1 < NITER) stage((it + 1) & 1);
        __syncthreads();
    }

    const int er = lane >> 2, ec = (lane & 3) * 2;
    #pragma unroll
    for (int mt = 0; mt < 2; mt++) {
        #pragma unroll
        for (int nt = 0; nt < 4; nt++) {
            const int row = m0 + wm + mt * 16 + er;
            const int col = wn + nt * 8 + ec;
            *(float2*)&LHWout[(size_t)row * ODIM + col] =
                make_float2(acc[mt][nt][0], acc[mt][nt][1]);
            *(float2*)&LHWout[(size_t)(row + 8) * ODIM + col] =
                make_float2(acc[mt][nt][2], acc[mt][nt][3]);
        }
    }
}

// ============================================================
// 9) H_pre = HW + sum_k Z_k @ Bs_k - 0.15*LHW ; soft-thr ; LayerNorm
// ============================================================
__global__ __launch_bounds__(256) void fuse_out(const float* __restrict__ thrP,
                                                const float* __restrict__ gamP,
                                                const float* __restrict__ betP,
                                                float* __restrict__ out) {
    __shared__ float sAt[16][68];   // Z chunk transposed [d][row]
    __shared__ float sB[16][132];   // Bs chunk [d][col]
    const int tid = threadIdx.x;
    const int tx = tid & 15, ty = tid >> 4;
    const int r0 = blockIdx.x * 64;
    float acc[4][8] = {};

    for (int k = 0; k < KHOP; k++) {
        for (int d0 = 0; d0 < DSUB; d0 += 16) {
            int ar = tid >> 2, ac = (tid & 3) * 4;
            float4 a = *(const float4*)&g_Z[k][r0 + ar][d0 + ac];
            sAt[ac + 0][ar] = a.x; sAt[ac + 1][ar] = a.y;
            sAt[ac + 2][ar] = a.z; sAt[ac + 3][ar] = a.w;
            int dl = tid >> 4, c8 = (tid & 15) * 8;
            float4 b1 = *(const float4*)&g_Bs[k][d0 + dl][c8];
            float4 b2 = *(const float4*)&g_Bs[k][d0 + dl][c8 + 4];
            *(float4*)&sB[dl][c8]     = b1;
            *(float4*)&sB[dl][c8 + 4] = b2;
            __syncthreads();
            #pragma unroll
            for (int kk = 0; kk < 16; kk++) {
                float ra[4], rb[8];
                *(float4*)&ra[0] = *(const float4*)&sAt[kk][ty * 4];
                *(float4*)&rb[0] = *(const float4*)&sB[kk][tx * 8];
                *(float4*)&rb[4] = *(const float4*)&sB[kk][tx * 8 + 4];
                #pragma unroll
                for (int i = 0; i < 4; i++)
                    #pragma unroll
                    for (int j = 0; j < 8; j++) acc[i][j] += ra[i] * rb[j];
            }
            __syncthreads();
        }
    }

    float thr_[8], gam_[8], bet_[8];
    #pragma unroll
    for (int j = 0; j < 8; j++) {
        int c = tx * 8 + j;
        thr_[j] = fabsf(__ldg(&thrP[c]));
        gam_[j] = __ldg(&gamP[c]);
        bet_[j] = __ldg(&betP[c]);
    }
    #pragma unroll
    for (int i = 0; i < 4; i++) {
        size_t row = r0 + ty * 4 + i;
        float4 hw1 = *(const float4*)&g_HW[row * ODIM + tx * 8];
        float4 hw2 = *(const float4*)&g_HW[row * ODIM + tx * 8 + 4];
        float4 lw1 = *(const float4*)&g_LHW[row * ODIM + tx * 8];
        float4 lw2 = *(const float4*)&g_LHW[row * ODIM + tx * 8 + 4];
        float bias[8] = {hw1.x - LAPSC * lw1.x, hw1.y - LAPSC * lw1.y,
                         hw1.z - LAPSC * lw1.z, hw1.w - LAPSC * lw1.w,
                         hw2.x - LAPSC * lw2.x, hw2.y - LAPSC * lw2.y,
                         hw2.z - LAPSC * lw2.z, hw2.w - LAPSC * lw2.w};
        float v[8], s = 0.f, q = 0.f;
        #pragma unroll
        for (int j = 0; j < 8; j++) {
            float p = acc[i][j] + bias[j];
            float ap = fabsf(p) - thr_[j];
            float val = ap > 0.f ? copysignf(ap, p) : 0.f;
            v[j] = val; s += val; q += val * val;
        }
        #pragma unroll
        for (int o = 8; o >= 1; o >>= 1) {
            s += __shfl_xor_sync(0xffffffffu, s, o);
            q += __shfl_xor_sync(0xffffffffu, q, o);
        }
        float mu = s * (1.f / 128.f);
        float var = q * (1.f / 128.f) - mu * mu;
        float rs = rsqrtf(var + LN_EPSF);
        float o_[8];
        #pragma unroll
        for (int j = 0; j < 8; j++) o_[j] = (v[j] - mu) * rs * gam_[j] + bet_[j];
        *(float4*)&out[row * ODIM + tx * 8]     = make_float4(o_[0], o_[1], o_[2], o_[3]);
        *(float4*)&out[row * ODIM + tx * 8 + 4] = make_float4(o_[4], o_[5], o_[6], o_[7]);
    }
}

// ============================================================
extern "C" void kernel_launch(void* const* d_in, const int* in_sizes, int n_in,
                              void* d_out, int out_size) {
    const float* H    = (const float*)d_in[0];
    const float* hop  = (const float*)d_in[1];
    const float* L    = (const float*)d_in[2];
    const float* Wst  = (const float*)d_in[3];
    const float* Wout = (const float*)d_in[4];
    const float* thr  = (const float*)d_in[5];
    const float* gam  = (const float*)d_in[6];
    const float* bet  = (const float*)d_in[7];
    const float* tau  = (const float*)d_in[8];
    float* out = (float*)d_out;
    float* out_tail = out + (size_t)NN * ODIM;

    float* d_HW;
    cudaGetSymbolAddress((void**)&d_HW, g_HW);
    float* d_LHW;
    cudaGetSymbolAddress((void**)&d_LHW, g_LHW);

    const int zsmem = 2 * 64 * 257 * 4;                           // 131584
    cudaFuncSetAttribute(compute_Z,  cudaFuncAttributeMaxDynamicSharedMemorySize, zsmem);
    cudaFuncSetAttribute(trisolve_B, cudaFuncAttributeMaxDynamicSharedMemorySize, TRI_SMEM);
    cudaFuncSetAttribute(gemmLHW,    cudaFuncAttributeMaxDynamicSharedMemorySize, G2_SMEM);

    compute_Z<<<dim3(128, KHOP), 256, zsmem>>>(hop, Wst);    // 1
    computeHW<<<128, 256>>>(H, Wout);                        // 2
    compute_G<<<dim3(32, KHOP), 256>>>();                    // 3
    computeWWo<<<KHOP, 256>>>(Wst, Wout);                    // 4
    chol_factor<<<KHOP, 256>>>();                            // 5
    gemmLHW<<<128, 256, G2_SMEM>>>(L, d_HW, d_LHW);          // 6  <- profiled
    finalize_w<<<1, 32>>>(tau, out_tail);                    // 7
    trisolve_B<<<KHOP, 128, TRI_SMEM>>>();                   // 8
    fuse_out<<<128, 256>>>(thr, gam, bet, out);              // 9
}